// round 1
// baseline (speedup 1.0000x reference)
#include <cuda_runtime.h>

// Problem constants (fixed by the reference)
#define B_SZ   16384
#define S_GRID 7
#define CELLS_PER_B   49            // 7*7
#define CH     30
#define N_CELLS (B_SZ * CELLS_PER_B)   // 802816
#define BLOCK  256
#define GRID_N (N_CELLS / BLOCK)       // 3136 exactly

#define CELL_PX 64.0f
#define IMG_PX  448.0f

__device__ __forceinline__ float4 decode_box(float p0, float p1, float p2, float p3,
                                             float gx, float gy) {
    float cx = p0 * CELL_PX + gx;
    float cy = p1 * CELL_PX + gy;
    float w  = p2 * IMG_PX;
    float h  = p3 * IMG_PX;
    float4 r;
    r.x = fminf(fmaxf(cx - w * 0.5f, 0.0f), IMG_PX);
    r.y = fminf(fmaxf(cy - h * 0.5f, 0.0f), IMG_PX);
    r.z = fminf(fmaxf(cx + w * 0.5f, 0.0f), IMG_PX);
    r.w = fminf(fmaxf(cy + h * 0.5f, 0.0f), IMG_PX);
    return r;
}

__device__ __forceinline__ float iou_fn(float4 a, float4 b) {
    float l  = fmaxf(a.x, b.x);
    float r  = fminf(a.z, b.z);
    float tt = fmaxf(a.y, b.y);
    float bo = fminf(a.w, b.w);
    bool m = (l < r) && (tt < bo);
    float inter = (r - l) * (bo - tt);
    float uni = (a.z - a.x) * (a.w - a.y) + (b.z - b.x) * (b.w - b.y);
    // predicated select: unselected NaN/Inf path is discarded by SEL
    return m ? inter / (uni - inter) : 0.0f;
}

__global__ void zero_out_kernel(float* out) { out[0] = 0.0f; }

__global__ __launch_bounds__(BLOCK) void yolo_loss_kernel(
    const float* __restrict__ inp,   // [B, 30, 7, 7]
    const float* __restrict__ tgt,   // [B, 7, 7, 30]  == [N_CELLS, 30]
    float* __restrict__ out)
{
    __shared__ float st[BLOCK * CH];      // target slab: 256 cells x 30 ch = 30720 B
    __shared__ float warp_sums[BLOCK / 32];

    const int n0 = blockIdx.x * BLOCK;

    // ---- stage target slab via coalesced float4 loads ----
    // base byte offset = n0*120, multiple of 16 since n0 % 256 == 0
    const float4* tg4 = reinterpret_cast<const float4*>(tgt + (size_t)n0 * CH);
    float4* st4 = reinterpret_cast<float4*>(st);
    #pragma unroll 2
    for (int i = threadIdx.x; i < (BLOCK * CH) / 4; i += BLOCK)
        st4[i] = __ldg(&tg4[i]);
    __syncthreads();

    // ---- per-cell compute ----
    const int n    = n0 + threadIdx.x;
    const int b    = n / CELLS_PER_B;
    const int cell = n - b * CELLS_PER_B;
    const int row  = cell / S_GRID;
    const int col  = cell - row * S_GRID;
    const float gx = (float)col * CELL_PX;
    const float gy = (float)row * CELL_PX;

    // input: channel-major, stride 49 per channel; contiguous across threads
    const float* xb = inp + (size_t)b * (CH * CELLS_PER_B) + cell;
    float x[CH];
    #pragma unroll
    for (int c = 0; c < CH; c++)
        x[c] = __ldg(&xb[c * CELLS_PER_B]);

    const float* t = st + threadIdx.x * CH;

    float4 pb1 = decode_box(x[0], x[1], x[2], x[3], gx, gy);
    float4 pb2 = decode_box(x[5], x[6], x[7], x[8], gx, gy);
    float4 tb1 = decode_box(t[0], t[1], t[2], t[3], gx, gy);
    float4 tb2 = decode_box(t[5], t[6], t[7], t[8], gx, gy);

    float iou1 = iou_fn(pb1, tb1);
    float iou2 = iou_fn(pb2, tb2);
    bool  mask = iou1 < iou2;
    float iou  = mask ? iou2 : iou1;

    float s0 = mask ? x[5] : x[0];
    float s1 = mask ? x[6] : x[1];
    float s2 = mask ? x[7] : x[2];
    float s3 = mask ? x[8] : x[3];
    float s4 = mask ? x[9] : x[4];

    float w = (t[4] == 1.0f) ? 1.0f : 0.0f;

    float d0 = s0 - t[0], d1 = s1 - t[1];
    float coord = d0 * d0 + d1 * d1;
    float e2 = sqrtf(s2) - sqrtf(t[2]);
    float e3 = sqrtf(s3) - sqrtf(t[3]);
    float size = e2 * e2 + e3 * e3;
    float dc = s4 - iou;
    float conf = dc * dc;
    float noobj = s4 * s4;

    float cls = 0.0f;
    #pragma unroll
    for (int c = 10; c < CH; c++) {
        float d = x[c] - t[c];
        cls += d * d;
    }

    float loss = w * (5.0f * coord + 5.0f * size + conf + cls)
               + (1.0f - w) * 0.5f * noobj;

    // ---- block reduction ----
    #pragma unroll
    for (int o = 16; o > 0; o >>= 1)
        loss += __shfl_down_sync(0xFFFFFFFFu, loss, o);

    const int lane = threadIdx.x & 31;
    const int wid  = threadIdx.x >> 5;
    if (lane == 0) warp_sums[wid] = loss;
    __syncthreads();

    if (threadIdx.x < (BLOCK / 32)) {
        float v = warp_sums[threadIdx.x];
        #pragma unroll
        for (int o = (BLOCK / 64); o > 0; o >>= 1)
            v += __shfl_down_sync(0xFFu, v, o);
        if (threadIdx.x == 0)
            atomicAdd(out, v);
    }
}

extern "C" void kernel_launch(void* const* d_in, const int* in_sizes, int n_in,
                              void* d_out, int out_size) {
    const float* inp = (const float*)d_in[0];   // [16384, 30, 7, 7]
    const float* tgt = (const float*)d_in[1];   // [16384, 7, 7, 30]
    float* out = (float*)d_out;                 // scalar

    zero_out_kernel<<<1, 1>>>(out);
    yolo_loss_kernel<<<GRID_N, BLOCK>>>(inp, tgt, out);
}

// round 2
// speedup vs baseline: 1.0770x; 1.0770x over previous
#include <cuda_runtime.h>
#include <cstdint>

// Problem constants (fixed by the reference)
#define B_SZ   16384
#define S_GRID 7
#define CELLS_PER_B   49            // 7*7
#define CH     30
#define N_CELLS (B_SZ * CELLS_PER_B)   // 802816
#define BLOCK  256
#define GRID_N (N_CELLS / BLOCK)       // 3136 exactly

#define CELL_PX 64.0f
#define IMG_PX  448.0f

// grid-wide accumulator (zero-initialized at module load; reset by last block
// each call -> deterministic across graph replays, no separate zeroing kernel)
__device__ float        g_acc;
__device__ unsigned int g_count;

__device__ __forceinline__ uint32_t smem_u32(const void* p) {
    uint32_t a;
    asm("{ .reg .u64 t; cvta.to.shared.u64 t, %1; cvt.u32.u64 %0, t; }"
        : "=r"(a) : "l"(p));
    return a;
}

__device__ __forceinline__ float4 decode_box(float p0, float p1, float p2, float p3,
                                             float gx, float gy) {
    float cx = p0 * CELL_PX + gx;
    float cy = p1 * CELL_PX + gy;
    float w  = p2 * IMG_PX;
    float h  = p3 * IMG_PX;
    float4 r;
    r.x = fminf(fmaxf(cx - w * 0.5f, 0.0f), IMG_PX);
    r.y = fminf(fmaxf(cy - h * 0.5f, 0.0f), IMG_PX);
    r.z = fminf(fmaxf(cx + w * 0.5f, 0.0f), IMG_PX);
    r.w = fminf(fmaxf(cy + h * 0.5f, 0.0f), IMG_PX);
    return r;
}

__device__ __forceinline__ float iou_fn(float4 a, float4 b) {
    float l  = fmaxf(a.x, b.x);
    float r  = fminf(a.z, b.z);
    float tt = fmaxf(a.y, b.y);
    float bo = fminf(a.w, b.w);
    bool m = (l < r) && (tt < bo);
    float inter = (r - l) * (bo - tt);
    float uni = (a.z - a.x) * (a.w - a.y) + (b.z - b.x) * (b.w - b.y);
    return m ? inter / (uni - inter) : 0.0f;
}

__global__ __launch_bounds__(BLOCK) void yolo_loss_kernel(
    const float* __restrict__ inp,   // [B, 30, 7, 7]
    const float* __restrict__ tgt,   // [B, 7, 7, 30]  == [N_CELLS, 30]
    float* __restrict__ out)
{
    __shared__ float st[BLOCK * CH];      // target slab: 256 cells x 30 ch = 30720 B
    __shared__ float warp_sums[BLOCK / 32];

    const int n0 = blockIdx.x * BLOCK;

    // ---- stage target slab via cp.async (no register round-trip) ----
    // base byte offset = n0*120B, 16B-aligned since n0 % 256 == 0
    {
        const float4* tg4 = reinterpret_cast<const float4*>(tgt + (size_t)n0 * CH);
        uint32_t st_base = smem_u32(st);
        #pragma unroll
        for (int k = 0; k < 8; k++) {
            int i = threadIdx.x + k * BLOCK;
            if (i < (BLOCK * CH) / 4) {
                asm volatile("cp.async.ca.shared.global [%0], [%1], 16;\n"
                             :: "r"(st_base + i * 16), "l"(tg4 + i));
            }
        }
        asm volatile("cp.async.commit_group;\n" ::: "memory");
    }

    // ---- issue all input loads while cp.async is in flight ----
    const int n    = n0 + threadIdx.x;
    const int b    = n / CELLS_PER_B;
    const int cell = n - b * CELLS_PER_B;
    const int row  = cell / S_GRID;
    const int col  = cell - row * S_GRID;
    const float gx = (float)col * CELL_PX;
    const float gy = (float)row * CELL_PX;

    // input: channel-major, stride 49 per channel; contiguous across threads
    const float* xb = inp + (size_t)b * (CH * CELLS_PER_B) + cell;
    float x[CH];
    #pragma unroll
    for (int c = 0; c < CH; c++)
        x[c] = __ldg(&xb[c * CELLS_PER_B]);

    asm volatile("cp.async.wait_group 0;\n" ::: "memory");
    __syncthreads();

    const float* t = st + threadIdx.x * CH;

    float4 pb1 = decode_box(x[0], x[1], x[2], x[3], gx, gy);
    float4 pb2 = decode_box(x[5], x[6], x[7], x[8], gx, gy);
    float4 tb1 = decode_box(t[0], t[1], t[2], t[3], gx, gy);
    float4 tb2 = decode_box(t[5], t[6], t[7], t[8], gx, gy);

    float iou1 = iou_fn(pb1, tb1);
    float iou2 = iou_fn(pb2, tb2);
    bool  mask = iou1 < iou2;
    float iou  = mask ? iou2 : iou1;

    float s0 = mask ? x[5] : x[0];
    float s1 = mask ? x[6] : x[1];
    float s2 = mask ? x[7] : x[2];
    float s3 = mask ? x[8] : x[3];
    float s4 = mask ? x[9] : x[4];

    float w = (t[4] == 1.0f) ? 1.0f : 0.0f;

    float d0 = s0 - t[0], d1 = s1 - t[1];
    float coord = d0 * d0 + d1 * d1;
    float e2 = sqrtf(s2) - sqrtf(t[2]);
    float e3 = sqrtf(s3) - sqrtf(t[3]);
    float size = e2 * e2 + e3 * e3;
    float dc = s4 - iou;
    float conf = dc * dc;
    float noobj = s4 * s4;

    float cls = 0.0f;
    #pragma unroll
    for (int c = 10; c < CH; c++) {
        float d = x[c] - t[c];
        cls += d * d;
    }

    float loss = w * (5.0f * coord + 5.0f * size + conf + cls)
               + (1.0f - w) * 0.5f * noobj;

    // ---- block reduction ----
    #pragma unroll
    for (int o = 16; o > 0; o >>= 1)
        loss += __shfl_down_sync(0xFFFFFFFFu, loss, o);

    const int lane = threadIdx.x & 31;
    const int wid  = threadIdx.x >> 5;
    if (lane == 0) warp_sums[wid] = loss;
    __syncthreads();

    if (threadIdx.x == 0) {
        float v = 0.0f;
        #pragma unroll
        for (int i = 0; i < BLOCK / 32; i++) v += warp_sums[i];

        atomicAdd(&g_acc, v);
        __threadfence();
        unsigned int done = atomicAdd(&g_count, 1u);
        if (done == GRID_N - 1) {
            out[0]  = g_acc;     // publish result
            g_acc   = 0.0f;      // reset for next graph replay
            g_count = 0u;
        }
    }
}

extern "C" void kernel_launch(void* const* d_in, const int* in_sizes, int n_in,
                              void* d_out, int out_size) {
    const float* inp = (const float*)d_in[0];   // [16384, 30, 7, 7]
    const float* tgt = (const float*)d_in[1];   // [16384, 7, 7, 30]
    float* out = (float*)d_out;                 // scalar

    yolo_loss_kernel<<<GRID_N, BLOCK>>>(inp, tgt, out);
}